// round 7
// baseline (speedup 1.0000x reference)
#include <cuda_runtime.h>
#include <cuda_bf16.h>
#include <cstdint>

// B=32, P=64, D=34, L=1048576
// inputs: preds [B, L] f32, gts [B, P, D, 3] f32   output: [B] f32
// out[b] = sum_{valid} |preds[b, idx] - val| / #persons-with-any-valid-dim

#define RB   32
#define RP   64
#define RD   34
#define RL   1048576
#define NPD  (RP * RD)            // 2176 entries per batch
#define CPB  2                    // CTAs per batch (fat CTAs, shallow tail)
#define EPC  (NPD / CPB)          // 1088 entries per CTA = 32 whole persons
#define PPC  (RP / CPB)           // 32 persons per CTA
#define NTHREADS 1024
#define NWARPS  (NTHREADS / 32)   // 32

// Zero-initialized scratch; last-arriving CTA reads-and-resets so every
// graph replay starts from zero.
__device__ float        g_sum[RB];
__device__ float        g_np[RB];
__device__ unsigned int g_cnt[RB];

__global__ __launch_bounds__(NTHREADS, 1)
void regl1_kernel(const float* __restrict__ preds,
                  const float* __restrict__ gts,
                  float* __restrict__ out)
{
    const int b    = blockIdx.x >> 1;      // batch
    const int c    = blockIdx.x & 1;       // half within batch
    const int tid  = threadIdx.x;
    const int base = c * EPC;

    __shared__ float s_any[PPC];           // per-person any-valid flag
    __shared__ float s_wsum[NWARPS];

    if (tid < PPC) s_any[tid] = 0.0f;
    __syncthreads();

    const float* __restrict__ g  = gts   + (size_t)b * NPD * 3;
    const float* __restrict__ pr = preds + (size_t)b * RL;

    // Entry 0: all 1024 threads.  Entry 1: threads < 64 (1088-1024).
    float val0, flg0, val1, flg1;
    unsigned idx0, idx1;
    {
        const int i = base + tid;
        val0 = g[i * 3 + 0];
        idx0 = (unsigned)(int)g[i * 3 + 1];
        flg0 = g[i * 3 + 2];
    }
    const bool has1 = (tid < EPC - NTHREADS);
    {
        const int i  = base + tid + NTHREADS;
        const int ii = has1 ? i : base;      // harmless in-bounds dummy
        val1 = g[ii * 3 + 0];
        idx1 = (unsigned)(int)g[ii * 3 + 1];
        flg1 = has1 ? g[ii * 3 + 2] : -1.0f;
    }

    // Unconditional gathers; clamp keeps address flag-independent + safe.
    const float gat0 = __ldg(pr + (idx0 < RL ? idx0 : RL - 1u));
    const float gat1 = __ldg(pr + (idx1 < RL ? idx1 : RL - 1u));

    float sum = 0.0f;
    if (flg0 > 0.0f) {
        sum += fabsf(gat0 - val0);
        s_any[(base + tid) / RD - c * PPC] = 1.0f;            // benign race
    }
    if (has1 && flg1 > 0.0f) {
        sum += fabsf(gat1 - val1);
        s_any[(base + tid + NTHREADS) / RD - c * PPC] = 1.0f;
    }

    // intra-warp reduction
    #pragma unroll
    for (int off = 16; off > 0; off >>= 1)
        sum += __shfl_down_sync(0xFFFFFFFFu, sum, off);

    const int warp = tid >> 5;
    const int lane = tid & 31;
    if (lane == 0) s_wsum[warp] = sum;
    __syncthreads();

    if (warp == 0) {
        float tot = s_wsum[lane];                      // NWARPS == 32
        #pragma unroll
        for (int off = 16; off > 0; off >>= 1)
            tot += __shfl_down_sync(0xFFFFFFFFu, tot, off);

        float np = s_any[lane];                        // PPC == 32
        #pragma unroll
        for (int off = 16; off > 0; off >>= 1)
            np += __shfl_down_sync(0xFFFFFFFFu, np, off);

        if (lane == 0) {
            // Release-ordered partial adds (no L1-flushing threadfence).
            asm volatile("red.release.gpu.global.add.f32 [%0], %1;"
                         :: "l"(&g_sum[b]), "f"(tot) : "memory");
            asm volatile("red.release.gpu.global.add.f32 [%0], %1;"
                         :: "l"(&g_np[b]), "f"(np) : "memory");
            unsigned ticket;
            asm volatile("atom.acq_rel.gpu.global.add.u32 %0, [%1], 1;"
                         : "=r"(ticket) : "l"(&g_cnt[b]) : "memory");
            if (ticket == CPB - 1) {
                const float s = atomicExch(&g_sum[b], 0.0f);
                const float n = atomicExch(&g_np[b],  0.0f);
                out[b] = s / n;            // reference guarantees n >= 1
                g_cnt[b] = 0u;             // ready for next replay
            }
        }
    }
}

extern "C" void kernel_launch(void* const* d_in, const int* in_sizes, int n_in,
                              void* d_out, int out_size)
{
    const float* preds = (const float*)d_in[0];
    const float* gts   = (const float*)d_in[1];
    float* out         = (float*)d_out;
    regl1_kernel<<<RB * CPB, NTHREADS>>>(preds, gts, out);
}

// round 8
// speedup vs baseline: 1.5556x; 1.5556x over previous
#include <cuda_runtime.h>
#include <cuda_bf16.h>
#include <cstdint>

// B=32, P=64, D=34, L=1048576
// inputs: preds [B, L] f32, gts [B, P, D, 3] f32   output: [B] f32
// out[b] = sum_{valid} |preds[b, idx] - val| / #persons-with-any-valid-dim

#define RB   32
#define RP   64
#define RD   34
#define RL   1048576
#define NPD  (RP * RD)            // 2176 entries per batch
#define NG   (NPD * 3)            // 6528 floats of gts per batch
#define NG4  (NG / 4)             // 1632 float4s
#define NTHREADS 1024
#define NWARPS  (NTHREADS / 32)   // 32

__global__ __launch_bounds__(NTHREADS, 1)
void regl1_kernel(const float* __restrict__ preds,
                  const float* __restrict__ gts,
                  float* __restrict__ out)
{
    const int b    = blockIdx.x;
    const int tid  = threadIdx.x;
    const int warp = tid >> 5;
    const int lane = tid & 31;

    __shared__ float sg[NG];            // staged gts triples (26112 B)
    __shared__ float s_any[RP];         // per-person any-valid flag
    __shared__ float s_wsum[NWARPS];

    if (tid < RP) s_any[tid] = 0.0f;

    // Coalesced float4 staging of gts: each 128B line touched exactly once.
    {
        const float4* __restrict__ g4 = (const float4*)(gts + (size_t)b * NG);
        float4* sg4 = (float4*)sg;
        sg4[tid] = g4[tid];                       // k = tid
        if (tid < NG4 - NTHREADS)                 // k = tid + 1024 (608 threads)
            sg4[tid + NTHREADS] = g4[tid + NTHREADS];
    }
    __syncthreads();

    const float* __restrict__ pr = preds + (size_t)b * RL;

    // Entries: e0 = tid (all), e1 = tid + 1024 (all),
    // e2 = 2048 + warp*4 + lane (4 lanes per warp -> balanced across warps).
    const int  e0 = tid;
    const int  e1 = tid + NTHREADS;
    const bool has2 = (lane < 4);
    const int  e2 = 2 * NTHREADS + (warp << 2) + lane;   // valid when has2

    // Addresses first (stride-3 smem reads: conflict-free), gathers ASAP.
    const unsigned i0 = (unsigned)(int)sg[3 * e0 + 1];
    const unsigned i1 = (unsigned)(int)sg[3 * e1 + 1];
    const unsigned i2 = has2 ? (unsigned)(int)sg[3 * e2 + 1] : 0u;

    const float gat0 = __ldg(pr + i0);
    const float gat1 = __ldg(pr + i1);
    const float gat2 = __ldg(pr + i2);

    const float val0 = sg[3 * e0 + 0], flg0 = sg[3 * e0 + 2];
    const float val1 = sg[3 * e1 + 0], flg1 = sg[3 * e1 + 2];
    const float val2 = has2 ? sg[3 * e2 + 0] : 0.0f;
    const float flg2 = has2 ? sg[3 * e2 + 2] : -1.0f;

    float sum = 0.0f;
    if (flg0 > 0.0f) { sum += fabsf(gat0 - val0); s_any[e0 / RD] = 1.0f; }
    if (flg1 > 0.0f) { sum += fabsf(gat1 - val1); s_any[e1 / RD] = 1.0f; }
    if (flg2 > 0.0f) { sum += fabsf(gat2 - val2); s_any[e2 / RD] = 1.0f; }

    // intra-warp reduction
    #pragma unroll
    for (int off = 16; off > 0; off >>= 1)
        sum += __shfl_down_sync(0xFFFFFFFFu, sum, off);

    if (lane == 0) s_wsum[warp] = sum;
    __syncthreads();

    if (warp == 0) {
        float tot = s_wsum[lane];                     // 32 warps
        #pragma unroll
        for (int off = 16; off > 0; off >>= 1)
            tot += __shfl_down_sync(0xFFFFFFFFu, tot, off);

        float np = s_any[lane] + s_any[lane + 32];    // 64 persons
        #pragma unroll
        for (int off = 16; off > 0; off >>= 1)
            np += __shfl_down_sync(0xFFFFFFFFu, np, off);

        if (lane == 0)
            out[b] = tot / np;        // reference guarantees np >= 1
    }
}

extern "C" void kernel_launch(void* const* d_in, const int* in_sizes, int n_in,
                              void* d_out, int out_size)
{
    const float* preds = (const float*)d_in[0];
    const float* gts   = (const float*)d_in[1];
    float* out         = (float*)d_out;
    regl1_kernel<<<RB, NTHREADS>>>(preds, gts, out);
}